// round 5
// baseline (speedup 1.0000x reference)
#include <cuda_runtime.h>
#include <cstdint>

// RGCNHighMem: out[dst] += feat[src] @ W[etype]
// v5: single-pass scatter into padded per-relation buckets; main kernel uses
// transposed lane mapping (4 edges/warp, 8 lanes/edge) so feat gather and
// red.add are line-cooperative (4 lines/instr, not 32); W in smem read as
// contiguous 128B broadcast rows; dup-pair feat staging read via LDS.128.

#define RELS   64
#define EPB    256          // edges per main-kernel block
#define SCHUNK 512          // edges per scatter block
#define CAP    8192         // per-relation bucket capacity (max expected ~3.4K)
#define MAXK   (CAP / EPB)  // 32 chunks per relation max

__device__ int g_cnt[RELS];
__device__ unsigned long long g_edges[RELS * CAP];  // packed (src | dst<<32)

// Single-pass scatter: block-local histogram -> one global reservation per
// relation -> rank-and-store packed edges into relation buckets.
__global__ __launch_bounds__(256)
void k_scatter(const int* __restrict__ src, const int* __restrict__ dst,
               const int* __restrict__ et, int E) {
    __shared__ int cnt[RELS], base[RELS];
    int tid = threadIdx.x;
    int b0 = blockIdx.x * SCHUNK;
    int b1 = min(E, b0 + SCHUNK);
    if (tid < RELS) cnt[tid] = 0;
    __syncthreads();

    int t0 = -1, t1 = -1;
    int e0 = b0 + tid, e1 = b0 + tid + 256;
    if (e0 < b1) { t0 = et[e0]; atomicAdd(&cnt[t0], 1); }
    if (e1 < b1) { t1 = et[e1]; atomicAdd(&cnt[t1], 1); }
    __syncthreads();

    if (tid < RELS) {
        int v = cnt[tid];
        base[tid] = v ? atomicAdd(&g_cnt[tid], v) : 0;
        cnt[tid] = 0;
    }
    __syncthreads();

    if (t0 >= 0) {
        int p = base[t0] + atomicAdd(&cnt[t0], 1);
        g_edges[t0 * CAP + p] =
            (unsigned long long)(unsigned)src[e0] |
            ((unsigned long long)(unsigned)dst[e0] << 32);
    }
    if (t1 >= 0) {
        int p = base[t1] + atomicAdd(&cnt[t1], 1);
        g_edges[t1 * CAP + p] =
            (unsigned long long)(unsigned)src[e1] |
            ((unsigned long long)(unsigned)dst[e1] << 32);
    }
}

// Main: block = (relation, chunk); 128 threads = 4 warps.
// Warp-iter: 4 edges. Lane (eh = l>>3, c = l&7) owns edge eh, cols 4c..4c+3.
// - gather: feat4[s*8+c] -> 4 lines per LDG.128 (cooperative)
// - stage:  dup-pairs (x,x,y,y) in smem, slot stride 17 float4 (conflict-free)
// - compute: LDS.128 feat (2 dup scalars) + LDS.128 W (contiguous 128B row,
//            4-way broadcast) + 4 FFMA2 per 2 input dims
// - scatter: red.global.add.v4 -> 4 lines per instr (cooperative)
__global__ __launch_bounds__(128, 8)
void k_main(const float4* __restrict__ feat4, const float4* __restrict__ W4,
            float* __restrict__ out) {
    int r = blockIdx.x >> 5;            // MAXK = 32
    int k = blockIdx.x & (MAXK - 1);
    int cnt = g_cnt[r];
    int segs = k * EPB;
    if (segs >= cnt) return;            // block-uniform: safe before barrier
    int sege = min(cnt, segs + EPB);
    const unsigned long long* eb = g_edges + (size_t)r * CAP;

    // W[r] (1024 floats) in smem, row-major [32 rows][8 float4].
    __shared__ float4 Wsh[256];
    // Stage: [4 warps][2 bufs][4 slots][17 float4]; slot = 16 dup-float4 + pad.
    __shared__ float4 stage[4 * 2 * 68];

    int tid = threadIdx.x;
    Wsh[tid]       = W4[r * 256 + tid];
    Wsh[tid + 128] = W4[r * 256 + tid + 128];
    __syncthreads();
    const ulonglong2* Ws2 = (const ulonglong2*)Wsh;   // [i][c] 16B quads

    int w = tid >> 5, l = tid & 31;
    int eh = l >> 3, c = l & 7;
    float4* wbase = stage + w * 136;     // this warp's 2 buffers

    int buf = 0;
    for (int e0 = segs + w * 4; e0 < sege; e0 += 16) {
        int e = e0 + eh;
        bool valid = e < sege;
        unsigned long long pk = eb[valid ? e : segs];
        int s = (int)(unsigned)pk;
        int d = (int)(pk >> 32);

        // Cooperative gather: 4 lines per LDG.128 across the warp.
        float4 f = feat4[s * 8 + c];

        // Stage dup-pairs: slot eh, 16 float4 of (x,x,y,y).
        float4* slot = wbase + buf * 68 + eh * 17;
        slot[c * 2]     = make_float4(f.x, f.x, f.y, f.y);
        slot[c * 2 + 1] = make_float4(f.z, f.z, f.w, f.w);
        __syncwarp();

        const ulonglong2* rp = (const ulonglong2*)slot;
        unsigned long long a0 = 0, a1 = 0;   // cols 4c..4c+1, 4c+2..4c+3
        #pragma unroll
        for (int i2 = 0; i2 < 16; i2++) {
            ulonglong2 fp = rp[i2];                      // dup x_{2i2}, x_{2i2+1}
            ulonglong2 w0 = Ws2[(2 * i2) * 8 + c];       // W row 2i2, quad c
            ulonglong2 w1 = Ws2[(2 * i2 + 1) * 8 + c];   // W row 2i2+1
            asm("fma.rn.f32x2 %0, %1, %2, %0;" : "+l"(a0) : "l"(fp.x), "l"(w0.x));
            asm("fma.rn.f32x2 %0, %1, %2, %0;" : "+l"(a1) : "l"(fp.x), "l"(w0.y));
            asm("fma.rn.f32x2 %0, %1, %2, %0;" : "+l"(a0) : "l"(fp.y), "l"(w1.x));
            asm("fma.rn.f32x2 %0, %1, %2, %0;" : "+l"(a1) : "l"(fp.y), "l"(w1.y));
        }

        if (valid) {
            unsigned ax, ay, az, aw;
            asm("mov.b64 {%0,%1}, %2;" : "=r"(ax), "=r"(ay) : "l"(a0));
            asm("mov.b64 {%0,%1}, %2;" : "=r"(az), "=r"(aw) : "l"(a1));
            float* p = out + (size_t)d * 32 + c * 4;
            // Cooperative scatter: 4 lines per red instr across the warp.
            asm volatile("red.global.add.v4.f32 [%0], {%1,%2,%3,%4};"
                         :: "l"(p),
                            "f"(__uint_as_float(ax)), "f"(__uint_as_float(ay)),
                            "f"(__uint_as_float(az)), "f"(__uint_as_float(aw))
                         : "memory");
        }
        buf ^= 1;   // double buffer: no second syncwarp needed
    }
}

extern "C" void kernel_launch(void* const* d_in, const int* in_sizes, int n_in,
                              void* d_out, int out_size) {
    const float* feat = (const float*)d_in[0];
    const float* W    = (const float*)d_in[1];
    const int*   src  = (const int*)d_in[2];
    const int*   dst  = (const int*)d_in[3];
    const int*   et   = (const int*)d_in[4];
    int E = in_sizes[2];

    void* cnt_addr = nullptr;
    cudaGetSymbolAddress(&cnt_addr, g_cnt);

    cudaMemsetAsync(d_out, 0, (size_t)out_size * sizeof(float), 0);
    cudaMemsetAsync(cnt_addr, 0, RELS * sizeof(int), 0);
    k_scatter<<<(E + SCHUNK - 1) / SCHUNK, 256>>>(src, dst, et, E);
    k_main<<<RELS * MAXK, 128>>>((const float4*)feat, (const float4*)W,
                                 (float*)d_out);
}

// round 6
// speedup vs baseline: 2.2966x; 2.2966x over previous
#include <cuda_runtime.h>
#include <cstdint>

// RGCNHighMem: out[dst] += feat[src] @ W[etype]
// v6: single-pass scatter (+ fused d_out zeroing); main kernel phases:
//   A: cooperative feat gather (4 rows/LDG.128) into per-warp smem stage
//   B: 2 edges/lane, 32 indep f32x2 acc chains, broadcast W-LDS feeds 4 FFMA2
//   C: acc transposed through stage, cooperative red.add.v4 (4 rows/instr)

#define RELS   64
#define EPB    256          // edges per main-kernel block (4 warps x 64)
#define SCHUNK 512          // edges per scatter block
#define CAP    8192         // per-relation bucket capacity (max expected ~3.4K)
#define MAXK   (CAP / EPB)  // 32 chunks per relation

__device__ int g_cnt[RELS];
__device__ unsigned long long g_edges[RELS * CAP];  // packed (src | dst<<32)

// Single-pass scatter + d_out zeroing (removes a separate memset launch).
__global__ __launch_bounds__(256)
void k_scatter(const int* __restrict__ src, const int* __restrict__ dst,
               const int* __restrict__ et, int E,
               float4* __restrict__ out4, int nout4) {
    __shared__ int cnt[RELS], base[RELS];
    int tid = threadIdx.x;

    // zero d_out (grid-strided float4)
    for (int i = blockIdx.x * 256 + tid; i < nout4; i += gridDim.x * 256)
        out4[i] = make_float4(0.f, 0.f, 0.f, 0.f);

    int b0 = blockIdx.x * SCHUNK;
    int b1 = min(E, b0 + SCHUNK);
    if (tid < RELS) cnt[tid] = 0;
    __syncthreads();

    int t0 = -1, t1 = -1;
    int e0 = b0 + tid, e1 = b0 + tid + 256;
    if (e0 < b1) { t0 = et[e0]; atomicAdd(&cnt[t0], 1); }
    if (e1 < b1) { t1 = et[e1]; atomicAdd(&cnt[t1], 1); }
    __syncthreads();

    if (tid < RELS) {
        int v = cnt[tid];
        base[tid] = v ? atomicAdd(&g_cnt[tid], v) : 0;
        cnt[tid] = 0;
    }
    __syncthreads();

    if (t0 >= 0) {
        int p = base[t0] + atomicAdd(&cnt[t0], 1);
        g_edges[t0 * CAP + p] =
            (unsigned long long)(unsigned)src[e0] |
            ((unsigned long long)(unsigned)dst[e0] << 32);
    }
    if (t1 >= 0) {
        int p = base[t1] + atomicAdd(&cnt[t1], 1);
        g_edges[t1 * CAP + p] =
            (unsigned long long)(unsigned)src[e1] |
            ((unsigned long long)(unsigned)dst[e1] << 32);
    }
}

__device__ __forceinline__ unsigned long long dup_u64(unsigned s) {
    unsigned long long d;
    asm("mov.b64 %0, {%1, %1};" : "=l"(d) : "r"(s));
    return d;
}

// Main: block = (relation, chunk); 128 threads = 4 warps; warp owns 64 edges.
__global__ __launch_bounds__(128, 4)
void k_main(const float4* __restrict__ feat4, const float4* __restrict__ W4,
            float* __restrict__ out) {
    int r = blockIdx.x >> 5;            // MAXK = 32
    int k = blockIdx.x & (MAXK - 1);
    int cnt = g_cnt[r];
    int segs = k * EPB;
    if (segs >= cnt) return;            // block-uniform
    int sege = min(cnt, segs + EPB);
    const unsigned long long* eb = g_edges + (size_t)r * CAP;

    __shared__ float4 Wsh[256];              // W[r]: [32 rows][8 quads]
    __shared__ float4 stage[4][64 * 9];      // per-warp: 64 rows, stride 9

    int tid = threadIdx.x;
    Wsh[tid]       = W4[r * 256 + tid];
    Wsh[tid + 128] = W4[r * 256 + tid + 128];
    __syncthreads();
    const ulonglong2* Ws2 = (const ulonglong2*)Wsh;

    int w = tid >> 5, l = tid & 31;
    int eh = l >> 3, c = l & 7;
    float4* st = stage[w];

    int e0 = segs + w * 64;
    if (e0 >= sege) return;                  // per-warp; only syncwarp below

    // ---- Phase A: cooperative gather of 64 feat rows ----
    #pragma unroll
    for (int g = 0; g < 16; g++) {
        int row = g * 4 + eh;
        int e = min(e0 + row, sege - 1);
        unsigned long long pk = eb[e];       // 8-lane dup -> 1 line
        int s = (int)(unsigned)pk;
        st[row * 9 + c] = feat4[s * 8 + c];  // 4 rows per LDG.128
    }
    __syncwarp();

    // ---- Phase B: 2 edges per lane (rows l and l+32) ----
    unsigned long long aA[16], aB[16];
    #pragma unroll
    for (int j = 0; j < 16; j++) { aA[j] = 0ULL; aB[j] = 0ULL; }

    const ulonglong2* rowA = (const ulonglong2*)(st + l * 9);
    const ulonglong2* rowB = (const ulonglong2*)(st + (l + 32) * 9);

    #pragma unroll
    for (int q = 0; q < 8; q++) {
        ulonglong2 fqA = rowA[q];
        ulonglong2 fqB = rowB[q];
        #pragma unroll
        for (int t = 0; t < 4; t++) {
            int i = 4 * q + t;
            unsigned sa, sb;
            {
                unsigned lo, hi;
                unsigned long long srcA = (t < 2) ? fqA.x : fqA.y;
                asm("mov.b64 {%0,%1}, %2;" : "=r"(lo), "=r"(hi) : "l"(srcA));
                sa = (t & 1) ? hi : lo;
                unsigned long long srcB = (t < 2) ? fqB.x : fqB.y;
                asm("mov.b64 {%0,%1}, %2;" : "=r"(lo), "=r"(hi) : "l"(srcB));
                sb = (t & 1) ? hi : lo;
            }
            unsigned long long dA = dup_u64(sa);
            unsigned long long dB = dup_u64(sb);
            #pragma unroll
            for (int h = 0; h < 8; h++) {
                ulonglong2 wv = Ws2[i * 8 + h];   // broadcast LDS.128
                asm("fma.rn.f32x2 %0, %1, %2, %0;"
                    : "+l"(aA[2 * h]) : "l"(dA), "l"(wv.x));
                asm("fma.rn.f32x2 %0, %1, %2, %0;"
                    : "+l"(aA[2 * h + 1]) : "l"(dA), "l"(wv.y));
                asm("fma.rn.f32x2 %0, %1, %2, %0;"
                    : "+l"(aB[2 * h]) : "l"(dB), "l"(wv.x));
                asm("fma.rn.f32x2 %0, %1, %2, %0;"
                    : "+l"(aB[2 * h + 1]) : "l"(dB), "l"(wv.y));
            }
        }
    }

    // Store accumulators back to stage (self-owned rows; no hazard yet).
    #pragma unroll
    for (int q = 0; q < 8; q++) {
        unsigned x, y, z, u;
        asm("mov.b64 {%0,%1}, %2;" : "=r"(x), "=r"(y) : "l"(aA[2 * q]));
        asm("mov.b64 {%0,%1}, %2;" : "=r"(z), "=r"(u) : "l"(aA[2 * q + 1]));
        st[l * 9 + q] = make_float4(__uint_as_float(x), __uint_as_float(y),
                                    __uint_as_float(z), __uint_as_float(u));
        asm("mov.b64 {%0,%1}, %2;" : "=r"(x), "=r"(y) : "l"(aB[2 * q]));
        asm("mov.b64 {%0,%1}, %2;" : "=r"(z), "=r"(u) : "l"(aB[2 * q + 1]));
        st[(l + 32) * 9 + q] = make_float4(__uint_as_float(x), __uint_as_float(y),
                                           __uint_as_float(z), __uint_as_float(u));
    }
    __syncwarp();

    // ---- Phase C: cooperative scatter, 4 dst rows per red.v4 ----
    #pragma unroll
    for (int g = 0; g < 16; g++) {
        int row = g * 4 + eh;
        int e = e0 + row;
        if (e < sege) {
            unsigned long long pk = eb[e];   // L1 hit
            int d = (int)(pk >> 32);
            float4 a = st[row * 9 + c];
            float* p = out + (size_t)d * 32 + c * 4;
            asm volatile("red.global.add.v4.f32 [%0], {%1,%2,%3,%4};"
                         :: "l"(p), "f"(a.x), "f"(a.y), "f"(a.z), "f"(a.w)
                         : "memory");
        }
    }
}

extern "C" void kernel_launch(void* const* d_in, const int* in_sizes, int n_in,
                              void* d_out, int out_size) {
    const float* feat = (const float*)d_in[0];
    const float* W    = (const float*)d_in[1];
    const int*   src  = (const int*)d_in[2];
    const int*   dst  = (const int*)d_in[3];
    const int*   et   = (const int*)d_in[4];
    int E = in_sizes[2];

    void* cnt_addr = nullptr;
    cudaGetSymbolAddress(&cnt_addr, g_cnt);

    cudaMemsetAsync(cnt_addr, 0, RELS * sizeof(int), 0);
    k_scatter<<<(E + SCHUNK - 1) / SCHUNK, 256>>>(src, dst, et, E,
                                                  (float4*)d_out, out_size / 4);
    k_main<<<RELS * MAXK, 128>>>((const float4*)feat, (const float4*)W,
                                 (float*)d_out);
}

// round 7
// speedup vs baseline: 2.4438x; 1.0641x over previous
#include <cuda_runtime.h>
#include <cstdint>

// RGCNHighMem: out[dst] += feat[src] @ W[etype]
// v7: v6 phase structure with column-split lanes to halve acc registers:
//   tile = 32 edges/warp; lane (m, p) owns edges {m, m+16}, cols 16p..16p+15.
//   A: cooperative feat gather (4 rows/LDG.128) -> smem stage (stride 9 f4)
//   B: 16 indep f32x2 acc chains/lane; W-LDS 2-addr broadcast, conflict-free
//   C: acc transposed through stage, cooperative red.add.v4 (4 rows/instr)
// occ 6 (launch_bounds), 2 tiles per warp per block (EPB 256).

#define RELS   64
#define EPB    256          // edges per main-kernel block (4 warps x 2 x 32)
#define SCHUNK 512          // edges per scatter block
#define CAP    8192         // per-relation bucket capacity (max expected ~3.4K)
#define MAXK   (CAP / EPB)  // 32 chunks per relation

__device__ int g_cnt[RELS];
__device__ unsigned long long g_edges[RELS * CAP];  // packed (src | dst<<32)

// Single-pass scatter + d_out zeroing.
__global__ __launch_bounds__(256)
void k_scatter(const int* __restrict__ src, const int* __restrict__ dst,
               const int* __restrict__ et, int E,
               float4* __restrict__ out4, int nout4) {
    __shared__ int cnt[RELS], base[RELS];
    int tid = threadIdx.x;

    for (int i = blockIdx.x * 256 + tid; i < nout4; i += gridDim.x * 256)
        out4[i] = make_float4(0.f, 0.f, 0.f, 0.f);

    int b0 = blockIdx.x * SCHUNK;
    int b1 = min(E, b0 + SCHUNK);
    if (tid < RELS) cnt[tid] = 0;
    __syncthreads();

    int t0 = -1, t1 = -1;
    int e0 = b0 + tid, e1 = b0 + tid + 256;
    if (e0 < b1) { t0 = et[e0]; atomicAdd(&cnt[t0], 1); }
    if (e1 < b1) { t1 = et[e1]; atomicAdd(&cnt[t1], 1); }
    __syncthreads();

    if (tid < RELS) {
        int v = cnt[tid];
        base[tid] = v ? atomicAdd(&g_cnt[tid], v) : 0;
        cnt[tid] = 0;
    }
    __syncthreads();

    if (t0 >= 0) {
        int p = base[t0] + atomicAdd(&cnt[t0], 1);
        g_edges[t0 * CAP + p] =
            (unsigned long long)(unsigned)src[e0] |
            ((unsigned long long)(unsigned)dst[e0] << 32);
    }
    if (t1 >= 0) {
        int p = base[t1] + atomicAdd(&cnt[t1], 1);
        g_edges[t1 * CAP + p] =
            (unsigned long long)(unsigned)src[e1] |
            ((unsigned long long)(unsigned)dst[e1] << 32);
    }
}

__device__ __forceinline__ unsigned long long dup_u64(unsigned s) {
    unsigned long long d;
    asm("mov.b64 %0, {%1, %1};" : "=l"(d) : "r"(s));
    return d;
}

__global__ __launch_bounds__(128, 6)
void k_main(const float4* __restrict__ feat4, const float4* __restrict__ W4,
            float* __restrict__ out) {
    int r = blockIdx.x >> 5;            // MAXK = 32
    int kk = blockIdx.x & (MAXK - 1);
    int cnt = g_cnt[r];
    int segs = kk * EPB;
    if (segs >= cnt) return;            // block-uniform
    int sege = min(cnt, segs + EPB);
    const unsigned long long* eb = g_edges + (size_t)r * CAP;

    __shared__ float4 Wsh[256];              // W[r]: [32 rows][8 quads]
    __shared__ float4 stage[4][32 * 9];      // per-warp: 32 rows, stride 9

    int tid = threadIdx.x;
    Wsh[tid]       = W4[r * 256 + tid];
    Wsh[tid + 128] = W4[r * 256 + tid + 128];
    __syncthreads();
    const ulonglong2* Ws2 = (const ulonglong2*)Wsh;

    int w = tid >> 5, l = tid & 31;
    int m = l & 15, p = l >> 4;          // edges {m, m+16}, cols 16p..16p+15
    int eh4 = l >> 3, c = l & 7;         // cooperative phases
    float4* st = stage[w];
    const ulonglong2* WsP = Ws2 + p * 4;

    #pragma unroll 1
    for (int t = 0; t < 2; t++) {
        int e0 = segs + w * 64 + t * 32;
        if (e0 >= sege) break;

        // ---- Phase A: cooperative gather of 32 feat rows ----
        #pragma unroll
        for (int g = 0; g < 8; g++) {
            int row = g * 4 + eh4;
            int e = min(e0 + row, sege - 1);
            unsigned long long pk = eb[e];          // 8-lane dup -> 1 line
            int s = (int)(unsigned)pk;
            st[row * 9 + c] = feat4[s * 8 + c];     // 4 rows per LDG.128
        }
        __syncwarp();

        // ---- Phase B: edges m, m+16; 16 f32x2 acc chains ----
        unsigned long long aA[8], aB[8];
        #pragma unroll
        for (int j = 0; j < 8; j++) { aA[j] = 0ULL; aB[j] = 0ULL; }

        const ulonglong2* rowA = (const ulonglong2*)(st + m * 9);
        const ulonglong2* rowB = (const ulonglong2*)(st + (m + 16) * 9);

        #pragma unroll
        for (int q = 0; q < 8; q++) {
            ulonglong2 fqA = rowA[q];
            ulonglong2 fqB = rowB[q];
            #pragma unroll
            for (int tt = 0; tt < 4; tt++) {
                int i = 4 * q + tt;
                unsigned lo, hi, sa, sb;
                unsigned long long srcA = (tt < 2) ? fqA.x : fqA.y;
                asm("mov.b64 {%0,%1}, %2;" : "=r"(lo), "=r"(hi) : "l"(srcA));
                sa = (tt & 1) ? hi : lo;
                unsigned long long srcB = (tt < 2) ? fqB.x : fqB.y;
                asm("mov.b64 {%0,%1}, %2;" : "=r"(lo), "=r"(hi) : "l"(srcB));
                sb = (tt & 1) ? hi : lo;
                unsigned long long dA = dup_u64(sa);
                unsigned long long dB = dup_u64(sb);
                #pragma unroll
                for (int hh = 0; hh < 4; hh++) {
                    ulonglong2 wv = WsP[i * 8 + hh];  // 2-addr broadcast LDS
                    asm("fma.rn.f32x2 %0, %1, %2, %0;"
                        : "+l"(aA[2 * hh]) : "l"(dA), "l"(wv.x));
                    asm("fma.rn.f32x2 %0, %1, %2, %0;"
                        : "+l"(aA[2 * hh + 1]) : "l"(dA), "l"(wv.y));
                    asm("fma.rn.f32x2 %0, %1, %2, %0;"
                        : "+l"(aB[2 * hh]) : "l"(dB), "l"(wv.x));
                    asm("fma.rn.f32x2 %0, %1, %2, %0;"
                        : "+l"(aB[2 * hh + 1]) : "l"(dB), "l"(wv.y));
                }
            }
        }

        // Store acc quads (cols 16p+4hh..+3) back to stage.
        #pragma unroll
        for (int hh = 0; hh < 4; hh++) {
            unsigned x, y, z, u;
            asm("mov.b64 {%0,%1}, %2;" : "=r"(x), "=r"(y) : "l"(aA[2 * hh]));
            asm("mov.b64 {%0,%1}, %2;" : "=r"(z), "=r"(u) : "l"(aA[2 * hh + 1]));
            st[m * 9 + p * 4 + hh] =
                make_float4(__uint_as_float(x), __uint_as_float(y),
                            __uint_as_float(z), __uint_as_float(u));
            asm("mov.b64 {%0,%1}, %2;" : "=r"(x), "=r"(y) : "l"(aB[2 * hh]));
            asm("mov.b64 {%0,%1}, %2;" : "=r"(z), "=r"(u) : "l"(aB[2 * hh + 1]));
            st[(m + 16) * 9 + p * 4 + hh] =
                make_float4(__uint_as_float(x), __uint_as_float(y),
                            __uint_as_float(z), __uint_as_float(u));
        }
        __syncwarp();

        // ---- Phase C: cooperative scatter, 4 dst rows per red.v4 ----
        #pragma unroll
        for (int g = 0; g < 8; g++) {
            int row = g * 4 + eh4;
            int e = e0 + row;
            if (e < sege) {
                unsigned long long pk = eb[e];       // L1 hit
                int d = (int)(pk >> 32);
                float4 a = st[row * 9 + c];
                float* pp = out + (size_t)d * 32 + c * 4;
                asm volatile("red.global.add.v4.f32 [%0], {%1,%2,%3,%4};"
                             :: "l"(pp), "f"(a.x), "f"(a.y), "f"(a.z), "f"(a.w)
                             : "memory");
            }
        }
        __syncwarp();   // stage reused by next tile's Phase A
    }
}

extern "C" void kernel_launch(void* const* d_in, const int* in_sizes, int n_in,
                              void* d_out, int out_size) {
    const float* feat = (const float*)d_in[0];
    const float* W    = (const float*)d_in[1];
    const int*   src  = (const int*)d_in[2];
    const int*   dst  = (const int*)d_in[3];
    const int*   et   = (const int*)d_in[4];
    int E = in_sizes[2];

    void* cnt_addr = nullptr;
    cudaGetSymbolAddress(&cnt_addr, g_cnt);

    cudaMemsetAsync(cnt_addr, 0, RELS * sizeof(int), 0);
    k_scatter<<<(E + SCHUNK - 1) / SCHUNK, 256>>>(src, dst, et, E,
                                                  (float4*)d_out, out_size / 4);
    k_main<<<RELS * MAXK, 128>>>((const float4*)feat, (const float4*)W,
                                 (float*)d_out);
}